// round 1
// baseline (speedup 1.0000x reference)
#include <cuda_runtime.h>
#include <cstdint>

#define NGRID 8192
#define NLAYER 24
#define NPERIODS 50
#define NOBS 4096
#define NC 200
#define NPAD 64          // padded N for GEMM
#define KSPLIT 8
#define KB (NGRID / KSPLIT)   // 1024 k-range per block
#define MT 64            // m tile
#define KC 16            // k chunk
#define VREF 3.0f
#define RAYF 0.92f

// ---------------- scratch (no allocation allowed) ----------------
__device__ float g_R[NGRID * NPAD];            // 2 MB: R[g][p] = 1/c_true, padded cols zero
__device__ float g_part[KSPLIT * NOBS * NPAD]; // 8.4 MB: k-split partial s_pred
__device__ float g_sum;

// ---------------- f32x2 helpers ----------------
typedef unsigned long long ull;
#define FMA2(acc, a, b) asm("fma.rn.f32x2 %0, %1, %2, %0;" : "+l"(acc) : "l"(a), "l"(b))
#define PACK2(d, x) asm("mov.b64 %0, {%1, %2};" : "=l"(d) : "f"(x), "f"(x))
#define UNPACK2(lo, hi, v) asm("mov.b64 {%0, %1}, %2;" : "=f"(lo), "=f"(hi) : "l"(v))

// ============ kernel 1: dispersion surrogate -> R = 1/c_true ============
__global__ void k_dispersion(const float* __restrict__ Vs,
                             const float* __restrict__ thick,
                             const float* __restrict__ periods) {
    __shared__ float w[NPERIODS][NLAYER];
    __shared__ float zc[NLAYER];
    int tid = threadIdx.x;
    if (tid == 0) {
        float c = 0.0f;
        for (int l = 0; l < NLAYER; l++) {
            float t = thick[l];
            zc[l] = c + 0.5f * t;
            c += t;
        }
        if (blockIdx.x == 0) g_sum = 0.0f;
    }
    __syncthreads();
    if (tid < NPERIODS) {
        float ds = VREF * periods[tid] / 3.0f;
        float s = 0.0f;
        for (int l = 0; l < NLAYER; l++) {
            float v = expf(-zc[l] / ds) * thick[l];
            w[tid][l] = v;
            s += v;
        }
        float inv = 1.0f / s;
        for (int l = 0; l < NLAYER; l++) w[tid][l] *= inv;
    }
    __syncthreads();

    int g = blockIdx.x * blockDim.x + tid;   // grid 32 * 256 = 8192 exactly
    float vs[NLAYER];
#pragma unroll
    for (int l = 0; l < NLAYER; l++) vs[l] = Vs[g * NLAYER + l];
#pragma unroll 1
    for (int p = 0; p < NPERIODS; p++) {
        float d = 0.0f;
#pragma unroll
        for (int l = 0; l < NLAYER; l++) d += w[p][l] * vs[l];
        g_R[g * NPAD + p] = 1.0f / (RAYF * d);
    }
    for (int p = NPERIODS; p < NPAD; p++) g_R[g * NPAD + p] = 0.0f;
}

// ============ kernel 2: k-split GEMM  part[kz] = A[:, krange] @ R[krange, :] ============
// grid (64, KSPLIT), 256 threads (16 n-threads x 16 m-threads), thread tile 4m x 4n (f32x2 pairs)
__global__ __launch_bounds__(256) void k_gemm(const float* __restrict__ A) {
    __shared__ __align__(16) float As[KC][MT + 4];   // [k][m], pad 68
    __shared__ __align__(16) float Rs[KC][NPAD + 4]; // [k][n], pad 68

    int tid = threadIdx.x;
    int tx = tid & 15;       // n group
    int ty = tid >> 4;       // m group
    int m0 = blockIdx.x * MT;
    int k0 = blockIdx.y * KB;

    // load mappings
    int lm  = tid >> 2;          // 0..63   A row within tile
    int lk4 = (tid & 3) * 4;     // 0,4,8,12 A k offset (float4)
    int rk  = tid >> 4;          // 0..15   R row within chunk
    int rc4 = (tid & 15) * 4;    // R col (float4)

    ull acc[4][2];
#pragma unroll
    for (int i = 0; i < 4; i++) { acc[i][0] = 0ull; acc[i][1] = 0ull; }

    const float* Arow = A + (size_t)(m0 + lm) * NGRID + k0 + lk4;
    const float* Rrow = g_R + (size_t)(k0 + rk) * NPAD + rc4;

    float4 aReg = *(const float4*)Arow;
    float4 rReg = *(const float4*)Rrow;

    for (int kb = 0; kb < KB; kb += KC) {
        // stage current chunk
        As[lk4 + 0][lm] = aReg.x;
        As[lk4 + 1][lm] = aReg.y;
        As[lk4 + 2][lm] = aReg.z;
        As[lk4 + 3][lm] = aReg.w;
        *(float4*)&Rs[rk][rc4] = rReg;
        __syncthreads();

        if (kb + KC < KB) {  // prefetch next chunk (latency overlapped with compute)
            aReg = *(const float4*)(Arow + kb + KC);
            rReg = *(const float4*)(g_R + (size_t)(k0 + kb + KC + rk) * NPAD + rc4);
        }

#pragma unroll
        for (int kk = 0; kk < KC; kk++) {
            float4 av = *(const float4*)&As[kk][ty * 4];
            ulonglong2 rr = *(const ulonglong2*)&Rs[kk][tx * 4];
            float am[4] = {av.x, av.y, av.z, av.w};
#pragma unroll
            for (int i = 0; i < 4; i++) {
                ull ai;
                PACK2(ai, am[i]);
                FMA2(acc[i][0], ai, rr.x);
                FMA2(acc[i][1], ai, rr.y);
            }
        }
        __syncthreads();
    }

    // epilogue: write partial tile (padded width 64, float4 coalesced)
#pragma unroll
    for (int i = 0; i < 4; i++) {
        float x0, x1, x2, x3;
        UNPACK2(x0, x1, acc[i][0]);
        UNPACK2(x2, x3, acc[i][1]);
        float4 v = make_float4(x0, x1, x2, x3);
        int m = m0 + ty * 4 + i;
        *(float4*)&g_part[((size_t)blockIdx.y * NOBS + m) * NPAD + tx * 4] = v;
    }
}

// ============ kernel 3: e_max scan + interp + sum ============
// one warp per (obs, period). grid 25600 x 256 -> 204800 warps exactly.
__global__ __launch_bounds__(256) void k_finalize(const float* __restrict__ energy,
                                                  const float* __restrict__ c_axis) {
    int gw = (blockIdx.x * blockDim.x + threadIdx.x) >> 5;
    int lane = threadIdx.x & 31;
    int o = gw / NPERIODS;
    int p = gw - o * NPERIODS;

    const float* e = energy + ((size_t)o * NPERIODS + p) * NC;
    float m = -1e30f;
    for (int i = lane; i < NC; i += 32) m = fmaxf(m, e[i]);
#pragma unroll
    for (int off = 16; off > 0; off >>= 1)
        m = fmaxf(m, __shfl_xor_sync(0xffffffffu, m, off));

    float contrib = 0.0f;
    if (lane == 0) {
        float s = 0.0f;
#pragma unroll
        for (int kz = 0; kz < KSPLIT; kz++)
            s += g_part[((size_t)kz * NOBS + o) * NPAD + p];
        float v = 1.0f / s;  // c_pred
        const float* c = c_axis + (size_t)o * NC;
        // searchsorted (side='left'): first idx with c[idx] >= v
        int lo = 0, hi = NC;
        while (lo < hi) {
            int mid = (lo + hi) >> 1;
            if (c[mid] < v) lo = mid + 1; else hi = mid;
        }
        int idx = lo < 1 ? 1 : (lo > NC - 1 ? NC - 1 : lo);
        float c0 = c[idx - 1], c1 = c[idx];
        float e0 = e[idx - 1], e1 = e[idx];
        float wgt = (v - c0) / (c1 - c0 + 1e-12f);
        float ei = e0 + wgt * (e1 - e0);
        contrib = m - ei;
    }

    __shared__ float sred[8];
    if (lane == 0) sred[threadIdx.x >> 5] = contrib;
    __syncthreads();
    if (threadIdx.x == 0) {
        float t = 0.0f;
#pragma unroll
        for (int wgi = 0; wgi < 8; wgi++) t += sred[wgi];
        atomicAdd(&g_sum, t);
    }
}

// ============ kernel 4: write output ============
__global__ void k_write(float* out) {
    out[0] = -g_sum;   // SIGMA = 1
}

extern "C" void kernel_launch(void* const* d_in, const int* in_sizes, int n_in,
                              void* d_out, int out_size) {
    const float* Vs      = (const float*)d_in[0];
    const float* A       = (const float*)d_in[1];
    const float* energy  = (const float*)d_in[2];
    const float* c_axis  = (const float*)d_in[3];
    const float* thick   = (const float*)d_in[4];
    const float* periods = (const float*)d_in[5];
    float* out = (float*)d_out;

    k_dispersion<<<NGRID / 256, 256>>>(Vs, thick, periods);
    k_gemm<<<dim3(NOBS / MT, KSPLIT), 256>>>(A);
    k_finalize<<<(NOBS * NPERIODS) / 8, 256>>>(energy, c_axis);
    k_write<<<1, 1>>>(out);
}

// round 4
// speedup vs baseline: 2.1119x; 2.1119x over previous
#include <cuda_runtime.h>
#include <cuda_bf16.h>
#include <cstdint>

#define NGRID 8192
#define NLAYER 24
#define NPERIODS 50
#define NOBS 4096
#define NC 200
#define NPAD 64
#define KSPLIT 8
#define KB (NGRID / KSPLIT)      // 1024 K per CTA
#define KCHUNK 64                // K per smem chunk (64 bf16 = 128B rows)
#define NCHUNK (KB / KCHUNK)     // 16
#define MT 128
#define BUFA_BYTES (MT * KCHUNK * 2)     // 16384
#define BUFB_BYTES (NPAD * KCHUNK * 2)   // 8192
#define BUFSTRIDE (BUFA_BYTES + BUFB_BYTES)  // 24576
#define VREF 3.0f
#define RAYF 0.92f

// ---------------- scratch (no allocation allowed) ----------------
__device__ __nv_bfloat16 g_Rt[NPAD * NGRID];    // [n=64][k=8192] bf16; rows 50..63 zero
__device__ float g_part[KSPLIT * NOBS * NPAD];  // k-split partial s_pred

// ---------------- helpers ----------------
__device__ __forceinline__ uint32_t smem_u32(const void* p) {
    uint32_t a;
    asm("{ .reg .u64 t; cvta.to.shared.u64 t, %1; cvt.u32.u64 %0, t; }" : "=r"(a) : "l"(p));
    return a;
}
#define CVTPK(r, lo, hi) asm("cvt.rn.satfinite.bf16x2.f32 %0, %1, %2;" : "=r"(r) : "f"(hi), "f"(lo))
#define LDSM4(r0, r1, r2, r3, a) \
    asm volatile("ldmatrix.sync.aligned.m8n8.x4.shared.b16 {%0,%1,%2,%3}, [%4];" \
        : "=r"(r0), "=r"(r1), "=r"(r2), "=r"(r3) : "r"(a))
#define MMA16816(c, a0, a1, a2, a3, b0, b1) \
    asm volatile("mma.sync.aligned.m16n8k16.row.col.f32.bf16.bf16.f32 " \
        "{%0,%1,%2,%3}, {%4,%5,%6,%7}, {%8,%9}, {%0,%1,%2,%3};" \
        : "+f"((c)[0]), "+f"((c)[1]), "+f"((c)[2]), "+f"((c)[3]) \
        : "r"(a0), "r"(a1), "r"(a2), "r"(a3), "r"(b0), "r"(b1))

// ============ kernel 1: dispersion surrogate -> Rt[p][g] = bf16(1/c_true[g][p]) ============
__global__ void k_dispersion(const float* __restrict__ Vs,
                             const float* __restrict__ thick,
                             const float* __restrict__ periods,
                             float* __restrict__ out) {
    __shared__ float w[NPERIODS][NLAYER + 1];
    __shared__ float zc[NLAYER];
    int tid = threadIdx.x;
    if (tid == 0) {
        float c = 0.0f;
        for (int l = 0; l < NLAYER; l++) {
            float t = thick[l];
            zc[l] = c + 0.5f * t;
            c += t;
        }
        if (blockIdx.x == 0) out[0] = 0.0f;   // finalize accumulates into out
    }
    __syncthreads();
    if (tid < NPERIODS) {
        float ds = VREF * periods[tid] / 3.0f;
        float s = 0.0f;
        for (int l = 0; l < NLAYER; l++) {
            float v = expf(-zc[l] / ds) * thick[l];
            w[tid][l] = v;
            s += v;
        }
        float inv = 1.0f / s;
        for (int l = 0; l < NLAYER; l++) w[tid][l] *= inv;
    }
    __syncthreads();

    int g = blockIdx.x * blockDim.x + tid;   // 32 * 256 = 8192 exactly
    float vs[NLAYER];
#pragma unroll
    for (int l = 0; l < NLAYER; l++) vs[l] = Vs[g * NLAYER + l];
#pragma unroll 1
    for (int p = 0; p < NPERIODS; p++) {
        float d = 0.0f;
#pragma unroll
        for (int l = 0; l < NLAYER; l++) d += w[p][l] * vs[l];
        g_Rt[p * NGRID + g] = __float2bfloat16(1.0f / (RAYF * d));
    }
#pragma unroll
    for (int p = NPERIODS; p < NPAD; p++) g_Rt[p * NGRID + g] = __float2bfloat16(0.0f);
}

// ============ kernel 2: HMMA bf16 k-split GEMM ============
// grid (32, 8), 256 threads (8 warps). CTA: part[kz][m0:m0+128][0:64] over K range 1024.
// Warp w computes m rows [w*16, w*16+16) x all 64 n via mma.m16n8k16.
__global__ __launch_bounds__(256, 2) void k_gemm(const float* __restrict__ A) {
    __shared__ __align__(1024) uint8_t smem[2 * BUFSTRIDE];   // 48KB double buffer
    uint32_t sb = smem_u32(smem);
    int tid = threadIdx.x, lane = tid & 31, wid = tid >> 5;
    int m0 = blockIdx.x * MT, k0 = blockIdx.y * KB;

    // ---- staging mappings (LDG/STS) ----
    int ar = tid >> 1, ah = (tid & 1) * 32;        // A: row 0..127, f32 col base {0,32}
    int bn = tid >> 2, bq = (tid & 3) * 16;        // B: row 0..63, bf16 col base
    const float* Ap = A + (size_t)(m0 + ar) * NGRID + k0 + ah;
    const __nv_bfloat16* Bp = g_Rt + (size_t)bn * NGRID + k0 + bq;
    uint32_t a_row = (uint32_t)(ar * 128), a_xor = (uint32_t)((ar & 7) << 4);
    uint32_t b_row = (uint32_t)(bn * 128), b_xor = (uint32_t)((bn & 7) << 4);

    // ---- ldmatrix mappings ----
    int li = lane >> 3, lr = lane & 7;
    int a_m = (wid << 4) + ((li & 1) << 3) + lr;               // m row within tile
    uint32_t la_row = (uint32_t)(a_m * 128);
    uint32_t la_xor = (uint32_t)((a_m & 7) << 4);
    uint32_t la_kh  = (uint32_t)((li >> 1) * 16);              // k-half byte offset
    int b_nb = ((li >> 1) << 3) + lr;                          // n row within 16-pair
    uint32_t lb_row = (uint32_t)(b_nb * 128);
    uint32_t lb_xor = (uint32_t)((b_nb & 7) << 4);
    uint32_t lb_kh  = (uint32_t)((li & 1) * 16);

    float acc[8][4];
#pragma unroll
    for (int j = 0; j < 8; j++)
#pragma unroll
        for (int i = 0; i < 4; i++) acc[j][i] = 0.0f;

    float4 a_reg[8];
    uint4 b_reg[2];
#pragma unroll
    for (int i = 0; i < 8; i++) a_reg[i] = *(const float4*)(Ap + i * 4);
    b_reg[0] = *(const uint4*)(Bp);
    b_reg[1] = *(const uint4*)(Bp + 8);

#pragma unroll 1
    for (int c = 0; c < NCHUNK; c++) {
        uint32_t bufA = sb + (uint32_t)(c & 1) * BUFSTRIDE;
        uint32_t bufB = bufA + BUFA_BYTES;

        // stage chunk c (convert A f32->bf16, XOR-swizzled stores)
#pragma unroll
        for (int i = 0; i < 4; i++) {
            float4 u = a_reg[2 * i], v = a_reg[2 * i + 1];
            uint4 o;
            CVTPK(o.x, u.x, u.y); CVTPK(o.y, u.z, u.w);
            CVTPK(o.z, v.x, v.y); CVTPK(o.w, v.z, v.w);
            uint32_t coff = (uint32_t)(ah * 2 + i * 16);
            *(uint4*)(uintptr_t)(smem + (bufA - sb) + a_row + (coff ^ a_xor)) = o;
        }
        {
            uint32_t coff = (uint32_t)(bq * 2);
            *(uint4*)(uintptr_t)(smem + (bufB - sb) + b_row + (coff ^ b_xor)) = b_reg[0];
            *(uint4*)(uintptr_t)(smem + (bufB - sb) + b_row + ((coff + 16) ^ b_xor)) = b_reg[1];
        }

        // prefetch chunk c+1 into registers (overlaps the MMA below)
        if (c + 1 < NCHUNK) {
            const float* Ap2 = Ap + (c + 1) * KCHUNK;
#pragma unroll
            for (int i = 0; i < 8; i++) a_reg[i] = *(const float4*)(Ap2 + i * 4);
            const __nv_bfloat16* Bp2 = Bp + (c + 1) * KCHUNK;
            b_reg[0] = *(const uint4*)(Bp2);
            b_reg[1] = *(const uint4*)(Bp2 + 8);
        }

        __syncthreads();   // chunk c staged for all warps

        // compute: 4 k16 steps x 8 n8 tiles
#pragma unroll
        for (int ks = 0; ks < 4; ks++) {
            uint32_t a0, a1, a2, a3;
            LDSM4(a0, a1, a2, a3, bufA + la_row + (((uint32_t)(ks * 32) + la_kh) ^ la_xor));
#pragma unroll
            for (int nt = 0; nt < 4; nt++) {
                uint32_t b0, b1, b2, b3;
                LDSM4(b0, b1, b2, b3,
                      bufB + (uint32_t)(nt * 2048) + lb_row +
                      (((uint32_t)(ks * 32) + lb_kh) ^ lb_xor));
                MMA16816(acc[2 * nt],     a0, a1, a2, a3, b0, b1);
                MMA16816(acc[2 * nt + 1], a0, a1, a2, a3, b2, b3);
            }
        }
        // next iter's STS targets the other buffer; its last readers passed the
        // sync above -> single sync per chunk is safe.
    }

    // epilogue: thread holds rows (m0+wid*16+gid) and (+8), cols 8j+2*tig
    int gid = lane >> 2, tig = lane & 3;
    int m = m0 + wid * 16 + gid;
    float* outp = g_part + ((size_t)blockIdx.y * NOBS + m) * NPAD;
#pragma unroll
    for (int j = 0; j < 8; j++) {
        *(float2*)(outp + j * 8 + tig * 2) = make_float2(acc[j][0], acc[j][1]);
        *(float2*)(outp + 8 * NPAD + j * 8 + tig * 2) = make_float2(acc[j][2], acc[j][3]);
    }
}

// ============ kernel 3: fused max scan + counting searchsorted + interp + sum ============
// one warp per (obs, period). 25600 blocks x 256 threads.
__global__ __launch_bounds__(256) void k_finalize(const float* __restrict__ energy,
                                                  const float* __restrict__ c_axis,
                                                  float* __restrict__ out) {
    int gw = (blockIdx.x * blockDim.x + threadIdx.x) >> 5;
    int lane = threadIdx.x & 31;
    int o = gw / NPERIODS;
    int p = gw - o * NPERIODS;

    // parallel partial reduction across lanes 0..7
    float s = 0.0f;
    if (lane < KSPLIT)
        s = g_part[((size_t)lane * NOBS + o) * NPAD + p];
#pragma unroll
    for (int off = 4; off > 0; off >>= 1) s += __shfl_xor_sync(0xffffffffu, s, off);
    float v = __shfl_sync(0xffffffffu, 1.0f / s, 0);   // c_pred

    const float* e = energy + ((size_t)o * NPERIODS + p) * NC;
    const float* c = c_axis + (size_t)o * NC;
    float m = -1e30f;
    int cnt = 0;
#pragma unroll
    for (int i = lane; i < NC; i += 32) {
        m = fmaxf(m, e[i]);
        cnt += (c[i] < v);
    }
#pragma unroll
    for (int off = 16; off > 0; off >>= 1) {
        m = fmaxf(m, __shfl_xor_sync(0xffffffffu, m, off));
        cnt += __shfl_xor_sync(0xffffffffu, cnt, off);
    }

    float contrib = 0.0f;
    if (lane == 0) {
        int idx = cnt < 1 ? 1 : (cnt > NC - 1 ? NC - 1 : cnt);  // searchsorted-left, clipped
        float c0 = c[idx - 1], c1 = c[idx];
        float e0 = e[idx - 1], e1 = e[idx];
        float wgt = (v - c0) / (c1 - c0 + 1e-12f);
        contrib = m - (e0 + wgt * (e1 - e0));
    }

    __shared__ float sred[8];
    if (lane == 0) sred[threadIdx.x >> 5] = contrib;
    __syncthreads();
    if (threadIdx.x == 0) {
        float t = 0.0f;
#pragma unroll
        for (int wgi = 0; wgi < 8; wgi++) t += sred[wgi];
        atomicAdd(out, -t);   // log_like = -sum / SIGMA^2, SIGMA = 1
    }
}

extern "C" void kernel_launch(void* const* d_in, const int* in_sizes, int n_in,
                              void* d_out, int out_size) {
    const float* Vs      = (const float*)d_in[0];
    const float* A       = (const float*)d_in[1];
    const float* energy  = (const float*)d_in[2];
    const float* c_axis  = (const float*)d_in[3];
    const float* thick   = (const float*)d_in[4];
    const float* periods = (const float*)d_in[5];
    float* out = (float*)d_out;

    k_dispersion<<<NGRID / 256, 256>>>(Vs, thick, periods, out);
    k_gemm<<<dim3(NOBS / MT, KSPLIT), 256>>>(A);
    k_finalize<<<(NOBS * NPERIODS) / 8, 256>>>(energy, c_axis, out);
}

// round 5
// speedup vs baseline: 2.2313x; 1.0566x over previous
#include <cuda_runtime.h>
#include <cuda_bf16.h>
#include <cstdint>

#define NGRID 8192
#define NLAYER 24
#define NPERIODS 50
#define NOBS 4096
#define NC 200
#define NPAD 64
#define KSPLIT 4
#define KB (NGRID / KSPLIT)      // 2048 K per CTA
#define KCHUNK 64
#define NCHUNK (KB / KCHUNK)     // 32
#define MT 128
#define NSTAGE 4
#define STAGE_A 32768            // 128 rows x 64 f32 x 4B
#define STAGE_B 8192             // 64 rows x 64 bf16 x 2B
#define STAGE (STAGE_A + STAGE_B)   // 40960
#define SMEM_TOT (NSTAGE * STAGE)   // 163840
#define VREF 3.0f
#define RAYF 0.92f

// ---------------- scratch (no allocation allowed) ----------------
__device__ __nv_bfloat16 g_Rt[NPAD * NGRID];    // [n=64][k=8192] bf16; rows 50..63 zero
__device__ float g_part[KSPLIT * NOBS * NPAD];  // k-split partial s_pred

// ---------------- helpers ----------------
__device__ __forceinline__ uint32_t smem_u32(const void* p) {
    uint32_t a;
    asm("{ .reg .u64 t; cvta.to.shared.u64 t, %1; cvt.u32.u64 %0, t; }" : "=r"(a) : "l"(p));
    return a;
}
#define CVTPK(r, lo, hi) asm("cvt.rn.satfinite.bf16x2.f32 %0, %1, %2;" : "=r"(r) : "f"(hi), "f"(lo))
#define LDSM4(r0, r1, r2, r3, a) \
    asm volatile("ldmatrix.sync.aligned.m8n8.x4.shared.b16 {%0,%1,%2,%3}, [%4];" \
        : "=r"(r0), "=r"(r1), "=r"(r2), "=r"(r3) : "r"(a))
#define MMA16816(c, a0, a1, a2, a3, b0, b1) \
    asm volatile("mma.sync.aligned.m16n8k16.row.col.f32.bf16.bf16.f32 " \
        "{%0,%1,%2,%3}, {%4,%5,%6,%7}, {%8,%9}, {%0,%1,%2,%3};" \
        : "+f"((c)[0]), "+f"((c)[1]), "+f"((c)[2]), "+f"((c)[3]) \
        : "r"(a0), "r"(a1), "r"(a2), "r"(a3), "r"(b0), "r"(b1))
#define CPA16(dst, src) asm volatile("cp.async.cg.shared.global [%0], [%1], 16;" :: "r"(dst), "l"(src) : "memory")
#define CPCOMMIT() asm volatile("cp.async.commit_group;" ::: "memory")
#define CPWAIT2()  asm volatile("cp.async.wait_group 2;" ::: "memory")

// ============ kernel 1: dispersion surrogate -> Rt[p][g] = bf16(1/c_true[g][p]) ============
// 256 CTAs x 256 threads; block = 32 g x 8 p-groups
__global__ __launch_bounds__(256) void k_dispersion(const float* __restrict__ Vs,
                                                    const float* __restrict__ thick,
                                                    const float* __restrict__ periods,
                                                    float* __restrict__ out) {
    __shared__ float w[NPERIODS][NLAYER];
    __shared__ float wsum[NPERIODS];
    __shared__ float zc[NLAYER];
    __shared__ float vs[32 * 25];                 // 25-stride pad -> conflict-free
    int tid = threadIdx.x;
    int g0 = blockIdx.x * 32;

    if (tid == 0) {
        float c = 0.0f;
        for (int l = 0; l < NLAYER; l++) {
            float t = thick[l];
            zc[l] = c + 0.5f * t;
            c += t;
        }
        if (blockIdx.x == 0) out[0] = 0.0f;       // finalize accumulates into out
    }
    __syncthreads();

    for (int idx = tid; idx < NPERIODS * NLAYER; idx += 256) {
        int p = idx / NLAYER, l = idx - p * NLAYER;
        float ds = VREF * periods[p] / 3.0f;
        w[p][l] = expf(-zc[l] / ds) * thick[l];
    }
    for (int idx = tid; idx < 32 * NLAYER; idx += 256) {
        int gl = idx / NLAYER, l = idx - gl * NLAYER;
        vs[gl * 25 + l] = Vs[(g0 + gl) * NLAYER + l];
    }
    __syncthreads();
    if (tid < NPERIODS) {
        float s = 0.0f;
#pragma unroll
        for (int l = 0; l < NLAYER; l++) s += w[tid][l];
        wsum[tid] = s;
    }
    __syncthreads();

    int gl = tid & 31, pg = tid >> 5;
#pragma unroll 1
    for (int p = pg; p < NPAD; p += 8) {
        float val = 0.0f;
        if (p < NPERIODS) {
            float d = 0.0f;
#pragma unroll
            for (int l = 0; l < NLAYER; l++) d += w[p][l] * vs[gl * 25 + l];
            val = wsum[p] / (RAYF * d);
        }
        g_Rt[p * NGRID + g0 + gl] = __float2bfloat16(val);
    }
}

// ============ kernel 2: cp.async multistage HMMA bf16 GEMM ============
// grid (32, 4) = 128 CTAs (one wave), 256 threads (8 warps, warp = m16 x n64).
__global__ __launch_bounds__(256, 1) void k_gemm(const float* __restrict__ A) {
    extern __shared__ __align__(128) char smem[];
    uint32_t sb = smem_u32(smem);
    int tid = threadIdx.x, lane = tid & 31, wid = tid >> 5;
    int m0 = blockIdx.x * MT, k0 = blockIdx.y * KB;

    // ---- producer mappings ----
    int ar = tid >> 1, haf = tid & 1;              // A: row 0..127, granule half
    int bn = tid >> 2;                             // B: row 0..63
    const float* srcA0 = A + (size_t)(m0 + ar) * NGRID + k0 + haf * 32;
    const __nv_bfloat16* srcB0 = g_Rt + (size_t)bn * NGRID + k0;
    uint32_t dA_row = (uint32_t)(ar * 256);
    uint32_t aXor = (uint32_t)((ar & 7) << 4);
    uint32_t dB_row = (uint32_t)(bn * 128);
    uint32_t bXor = (uint32_t)((bn & 7) << 4);
    int bg0 = (tid & 3) * 2;

    // ---- consumer mappings ----
    int gid = lane >> 2, tig = lane & 3;
    uint32_t rowA0 = (uint32_t)((wid * 16 + gid) * 256);
    uint32_t rowA1 = rowA0 + 8 * 256;
    uint32_t sub = (uint32_t)((tig & 1) * 8);
    int gbase = tig >> 1;
    int li = lane >> 3, lr = lane & 7;
    int b_nb = ((li >> 1) << 3) + lr;
    uint32_t lb_row = (uint32_t)(b_nb * 128);
    uint32_t lb_xor = (uint32_t)((b_nb & 7) << 4);
    uint32_t lb_kh = (uint32_t)((li & 1) * 16);

    float acc[8][4];
#pragma unroll
    for (int j = 0; j < 8; j++)
#pragma unroll
        for (int i = 0; i < 4; i++) acc[j][i] = 0.0f;

    auto issue = [&](int c) {
        uint32_t buf = sb + (uint32_t)(c & (NSTAGE - 1)) * STAGE;
        const float* sA = srcA0 + c * KCHUNK;
#pragma unroll
        for (int i = 0; i < 8; i++) {
            uint32_t g = (uint32_t)(haf * 8 + i);
            CPA16(buf + dA_row + ((g << 4) ^ aXor), sA + i * 4);
        }
        uint32_t bufB = buf + STAGE_A;
        const __nv_bfloat16* sB = srcB0 + c * KCHUNK;
#pragma unroll
        for (int i = 0; i < 2; i++) {
            uint32_t g = (uint32_t)(bg0 + i);
            CPA16(bufB + dB_row + ((g << 4) ^ bXor), sB + g * 8);
        }
    };

    // prologue: stages 0..2 in flight
#pragma unroll
    for (int s = 0; s < NSTAGE - 1; s++) { issue(s); CPCOMMIT(); }

#pragma unroll 1
    for (int c = 0; c < NCHUNK; c++) {
        CPWAIT2();            // stage c landed
        __syncthreads();      // and all warps done reading buffer (c-1)%4
        if (c + NSTAGE - 1 < NCHUNK) issue(c + NSTAGE - 1);
        CPCOMMIT();

        uint32_t bufA = sb + (uint32_t)(c & (NSTAGE - 1)) * STAGE;
        uint32_t bufB = bufA + STAGE_A;
        const char* pA = smem + (size_t)(c & (NSTAGE - 1)) * STAGE;
#pragma unroll
        for (int ks = 0; ks < 4; ks++) {
            int gp0 = ks * 4 + gbase;
            uint32_t x0 = (uint32_t)((gp0 ^ gid) << 4);
            uint32_t x2 = (uint32_t)(((gp0 + 2) ^ gid) << 4);
            float2 v0 = *(const float2*)(pA + rowA0 + x0 + sub);
            float2 v1 = *(const float2*)(pA + rowA1 + x0 + sub);
            float2 v2 = *(const float2*)(pA + rowA0 + x2 + sub);
            float2 v3 = *(const float2*)(pA + rowA1 + x2 + sub);
            uint32_t a0, a1, a2, a3;
            CVTPK(a0, v0.x, v0.y);
            CVTPK(a1, v1.x, v1.y);
            CVTPK(a2, v2.x, v2.y);
            CVTPK(a3, v3.x, v3.y);
#pragma unroll
            for (int nt = 0; nt < 4; nt++) {
                uint32_t b0, b1, b2, b3;
                LDSM4(b0, b1, b2, b3,
                      bufB + (uint32_t)(nt * 2048) + lb_row +
                      (((uint32_t)(ks * 32) + lb_kh) ^ lb_xor));
                MMA16816(acc[2 * nt],     a0, a1, a2, a3, b0, b1);
                MMA16816(acc[2 * nt + 1], a0, a1, a2, a3, b2, b3);
            }
        }
    }

    // epilogue: thread holds rows (m0+wid*16+gid, +8), cols 8j+2*tig
    int m = m0 + wid * 16 + gid;
    float* outp = g_part + ((size_t)blockIdx.y * NOBS + m) * NPAD;
#pragma unroll
    for (int j = 0; j < 8; j++) {
        *(float2*)(outp + j * 8 + tig * 2) = make_float2(acc[j][0], acc[j][1]);
        *(float2*)(outp + 8 * NPAD + j * 8 + tig * 2) = make_float2(acc[j][2], acc[j][3]);
    }
}

// ============ kernel 3: fused max scan + counting searchsorted + interp + sum ============
// one warp per (obs, period). 25600 blocks x 256 threads.
__global__ __launch_bounds__(256) void k_finalize(const float* __restrict__ energy,
                                                  const float* __restrict__ c_axis,
                                                  float* __restrict__ out) {
    int gw = (blockIdx.x * blockDim.x + threadIdx.x) >> 5;
    int lane = threadIdx.x & 31;
    int o = gw / NPERIODS;
    int p = gw - o * NPERIODS;

    float s = (lane < KSPLIT) ? g_part[((size_t)lane * NOBS + o) * NPAD + p] : 0.0f;
    s += __shfl_xor_sync(0xffffffffu, s, 2);
    s += __shfl_xor_sync(0xffffffffu, s, 1);
    float v = 1.0f / __shfl_sync(0xffffffffu, s, 0);   // c_pred

    const float* e = energy + ((size_t)o * NPERIODS + p) * NC;
    const float* c = c_axis + (size_t)o * NC;
    const float4* e4 = (const float4*)e;
    const float4* c4 = (const float4*)c;
    float m = -1e30f;
    int cnt = 0;
#pragma unroll
    for (int i = lane; i < NC / 4; i += 32) {
        float4 f = e4[i];
        m = fmaxf(fmaxf(fmaxf(m, f.x), fmaxf(f.y, f.z)), f.w);
        float4 g = c4[i];
        cnt += (g.x < v) + (g.y < v) + (g.z < v) + (g.w < v);
    }
#pragma unroll
    for (int off = 16; off > 0; off >>= 1) {
        m = fmaxf(m, __shfl_xor_sync(0xffffffffu, m, off));
        cnt += __shfl_xor_sync(0xffffffffu, cnt, off);
    }

    float contrib = 0.0f;
    if (lane == 0) {
        int idx = cnt < 1 ? 1 : (cnt > NC - 1 ? NC - 1 : cnt);  // searchsorted-left, clipped
        float c0 = c[idx - 1], c1 = c[idx];
        float e0 = e[idx - 1], e1 = e[idx];
        float wgt = (v - c0) / (c1 - c0 + 1e-12f);
        contrib = m - (e0 + wgt * (e1 - e0));
    }

    __shared__ float sred[8];
    if (lane == 0) sred[threadIdx.x >> 5] = contrib;
    __syncthreads();
    if (threadIdx.x == 0) {
        float t = 0.0f;
#pragma unroll
        for (int wgi = 0; wgi < 8; wgi++) t += sred[wgi];
        atomicAdd(out, -t);   // log_like = -sum / SIGMA^2, SIGMA = 1
    }
}

extern "C" void kernel_launch(void* const* d_in, const int* in_sizes, int n_in,
                              void* d_out, int out_size) {
    const float* Vs      = (const float*)d_in[0];
    const float* A       = (const float*)d_in[1];
    const float* energy  = (const float*)d_in[2];
    const float* c_axis  = (const float*)d_in[3];
    const float* thick   = (const float*)d_in[4];
    const float* periods = (const float*)d_in[5];
    float* out = (float*)d_out;

    cudaFuncSetAttribute(k_gemm, cudaFuncAttributeMaxDynamicSharedMemorySize, SMEM_TOT);

    k_dispersion<<<NGRID / 32, 256>>>(Vs, thick, periods, out);
    k_gemm<<<dim3(NOBS / MT, KSPLIT), 256, SMEM_TOT>>>(A);
    k_finalize<<<(NOBS * NPERIODS) / 8, 256>>>(energy, c_axis, out);
}